// round 14
// baseline (speedup 1.0000x reference)
#include <cuda_runtime.h>
#include <cuda_fp16.h>
#include <cstdint>

// Problem constants
#define NB   16          // batch
#define TT   255         // teacher length (T-1)
#define UU   1024        // GRU units
#define VV   32000       // vocab
#define EE   256         // emb dim
#define LATD 512         // latent dim
#define MROWS (NB*TT)    // 4080
#define MPAD 4096
#define N3   (3*UU)      // 3072

#define GRU_BLOCKS 64
#define OUT_BLOCKS 84
#define FUSED_BLOCKS (GRU_BLOCKS+OUT_BLOCKS)
#define NTILES (32*125)                      // 4000 output tiles (m 0..31, nb 0..124)
#define NXTILES (32*24)                      // 768 xproj tiles (m 0..31, n 0..23)
#define UPC 16                               // units per CTA
#define SCSTRIDE 52
#define ASTRIDE 136                          // padded halves per (warp,batch) row
#define AWARP   (16*ASTRIDE)                 // halves per warp slice

// ---------------- device scratch (no allocs allowed) ----------------
__device__ __align__(128) __half g_hfp[2][NB*UU];     // fp16 hidden state, ping-pong
__device__ float g_xproj[(size_t)MROWS*N3];           // x @ gru_kernel + b0
__device__ __align__(128) __half g_Ah[(size_t)MPAD*UU];   // fp16 GRU outputs, row = t*16+b
__device__ __align__(128) __half g_Wh[(size_t)VV*UU];     // fp16 out_W^T  [V][U]
__device__ __align__(128) __half g_embh[(size_t)VV*EE];   // fp16 emb
__device__ __align__(128) __half g_gkT[(size_t)N3*EE];    // fp16 gru_kernel^T [3072][256]
__device__ __align__(128) __half g_rkTh[(size_t)N3*UU];   // fp16 gru_rkernel^T [3072][1024]
__device__ int   g_arow[MROWS];
__device__ unsigned char g_flag[MROWS];
__device__ __align__(256) unsigned g_cnt8[8][64];     // two-level barrier counters (256B apart)
__device__ unsigned g_tile;                           // output tile work queue
__device__ unsigned g_xtile;                          // xproj tile work queue
__device__ unsigned g_xdone;                          // xproj tiles completed
__device__ unsigned g_wdone;                          // convW slices completed

// ---------------- PTX helpers ----------------
__device__ __forceinline__ uint32_t smem_to_u32(const void* p){
    uint32_t a;
    asm("{ .reg .u64 t; cvta.to.shared.u64 t, %1; cvt.u32.u64 %0, t; }" : "=r"(a) : "l"(p));
    return a;
}
__device__ __forceinline__ void cp16(uint32_t s, const void* g){
    asm volatile("cp.async.cg.shared.global [%0], [%1], 16;" :: "r"(s), "l"(g));
}
__device__ __forceinline__ void cp_commit(){ asm volatile("cp.async.commit_group;" ::: "memory"); }
template<int N> __device__ __forceinline__ void cp_wait(){
    asm volatile("cp.async.wait_group %0;" :: "n"(N) : "memory");
}
__device__ __forceinline__ void ldsm4(uint32_t* r, uint32_t addr){
    asm volatile("ldmatrix.sync.aligned.m8n8.x4.shared.b16 {%0,%1,%2,%3}, [%4];"
        : "=r"(r[0]),"=r"(r[1]),"=r"(r[2]),"=r"(r[3]) : "r"(addr));
}
__device__ __forceinline__ void mma16816(float* c, const uint32_t* a, const uint32_t* b){
    asm volatile("mma.sync.aligned.m16n8k16.row.col.f32.f16.f16.f32 "
        "{%0,%1,%2,%3}, {%4,%5,%6,%7}, {%8,%9}, {%0,%1,%2,%3};"
        : "+f"(c[0]), "+f"(c[1]), "+f"(c[2]), "+f"(c[3])
        : "r"(a[0]), "r"(a[1]), "r"(a[2]), "r"(a[3]), "r"(b[0]), "r"(b[1]));
}
__device__ __forceinline__ void red_rel(unsigned* p){
    asm volatile("red.release.gpu.add.u32 [%0], 1;" :: "l"(p) : "memory");
}
__device__ __forceinline__ unsigned ld_acq(const unsigned* p){
    unsigned v;
    asm volatile("ld.acquire.gpu.u32 %0, [%1];" : "=r"(v) : "l"(p) : "memory");
    return v;
}

// two-level grid barrier: 8 counters (8 CTAs each), threads 0-7 spin one counter each.
__device__ __forceinline__ void gru_barrier2(int bl, int t){
    __syncthreads();
    if (threadIdx.x == 0) red_rel(&g_cnt8[bl & 7][0]);
    if (threadIdx.x < 8){
        unsigned target = (unsigned)(GRU_BLOCKS/8)*(unsigned)(t+1);
        const unsigned* p = &g_cnt8[threadIdx.x][0];
        while (ld_acq(p) < target) {}
    }
    __syncthreads();
}

// out-role readiness: all 8 counters >= min(64*(m+1), 8*TT)
__device__ __forceinline__ void wait_tile_ready(int m){
    if (threadIdx.x < 8){
        unsigned target = 64u*(unsigned)(m+1);
        unsigned maxt = 8u*(unsigned)TT;
        if (target > maxt) target = maxt;
        const unsigned* p = &g_cnt8[threadIdx.x][0];
        while (ld_acq(p) < target) __nanosleep(256);
    }
    __syncthreads();
}

// ---------------- fused prep kernel (no convW — moved into fused) ----------------
#define PB_PREP 1
#define PB_EMB  8000
#define PB_GKT  768
#define PB_H0   64
#define PB_RKT  3072
#define PB_TOTAL (PB_PREP+PB_EMB+PB_GKT+PB_H0+PB_RKT)

__global__ void prep_all(const float* __restrict__ lat, const float* __restrict__ dW,
                         const float* __restrict__ db,  const int* __restrict__ tok,
                         const float* __restrict__ emb, const float* __restrict__ gk,
                         const float* __restrict__ grk){
    __shared__ float tile[32][33];
    int bid = blockIdx.x;
    const int tid = threadIdx.x;
    const int tx = tid & 31, ty = tid >> 5;

    if (bid < PB_PREP){
        if (tid < 8) g_cnt8[tid][0] = 0;
        if (tid == 8){ g_tile = 0; g_xtile = 0; g_xdone = 0; g_wdone = 0; }
        if (tid >= 32 && tid < 32+NB){
            int b = tid - 32;
            unsigned char f = 0;
            for (int t=0;t<TT;t++){
                f |= (tok[b*256 + t] != 0) ? 1 : 0;
                g_flag[b*TT + t] = f;
            }
        }
        for (int m=tid; m<MROWS; m+=256){
            int v = tok[(m/TT)*256 + (m%TT)];
            if (v < 0) v = 0;
            if (v >= VV) v = VV-1;
            g_arow[m] = v;
        }
        return;
    }
    bid -= PB_PREP;

    if (bid < PB_EMB){
        int i = bid*256 + tid;
        float4 v = ((const float4*)emb)[i];
        __half2* dst = (__half2*)g_embh;
        dst[i*2+0] = __floats2half2_rn(v.x, v.y);
        dst[i*2+1] = __floats2half2_rn(v.z, v.w);
        return;
    }
    bid -= PB_EMB;

    if (bid < PB_GKT){
        int n0 = (bid % 96)*32, k0 = (bid / 96)*32;
        #pragma unroll
        for (int i=ty; i<32; i+=8)
            tile[i][tx] = gk[(size_t)(k0+i)*N3 + n0+tx];
        __syncthreads();
        #pragma unroll
        for (int i=ty; i<32; i+=8)
            g_gkT[(size_t)(n0+i)*EE + k0+tx] = __float2half(tile[tx][i]);
        return;
    }
    bid -= PB_GKT;

    if (bid < PB_H0){
        int o = bid*256 + tid;
        int b = o >> 10, u = o & (UU-1);
        float acc = db[u];
        const float* lrow = lat + b*LATD;
        #pragma unroll 8
        for (int k=0;k<LATD;k++) acc = fmaf(lrow[k], dW[(size_t)k*UU + u], acc);
        g_hfp[0][b*UU + u] = __float2half(acc);
        return;
    }
    bid -= PB_H0;

    {   // convRkT
        int n0 = (bid % 96)*32, k0 = (bid / 96)*32;
        #pragma unroll
        for (int i=ty; i<32; i+=8)
            tile[i][tx] = grk[(size_t)(k0+i)*N3 + n0+tx];
        __syncthreads();
        #pragma unroll
        for (int i=ty; i<32; i+=8)
            g_rkTh[(size_t)(n0+i)*UU + k0+tx] = __float2half(tile[tx][i]);
        return;
    }
}

// ---------------- HMMA tile constants ----------------
#define HG_STRIDE 72
#define HG_BUFB   (128*HG_STRIDE*2)       // 18432
#define OG_ABUF   HG_BUFB
#define OG_BBUF   (256*HG_STRIDE*2)       // 36864
#define OG_SMEM   (3*OG_ABUF + 3*OG_BBUF) // 165888

// ---------------- xproj tile (128x128, K=256, gathered A) ----------------
__device__ void xp_tile(char* sm, uint32_t sb, int tid, int lane, int wid,
                        int m0, int n0, const float* __restrict__ bias0,
                        float* __restrict__ C){
    const int wm = wid >> 2, wn = wid & 3;

    const __half* aptr[4];
    int asegs[4];
    #pragma unroll
    for (int i=0;i<4;i++){
        int idx = tid + i*256;
        int row = idx >> 3; asegs[i] = idx & 7;
        int grow = m0 + row;
        int tokv = (grow < MROWS) ? g_arow[grow] : 0;
        aptr[i] = g_embh + (size_t)tokv*EE;
    }
    auto loadA = [&](int kc, int st){
        uint32_t base = sb + st*HG_BUFB;
        #pragma unroll
        for (int i=0;i<4;i++){
            int idx = tid + i*256;
            int row = idx >> 3;
            cp16(base + (uint32_t)(row*HG_STRIDE + asegs[i]*8)*2,
                 aptr[i] + kc*64 + asegs[i]*8);
        }
    };
    auto loadB = [&](int kc, int st){
        const __half* gB = g_gkT + (size_t)n0*EE + kc*64;
        uint32_t base = sb + (3+st)*HG_BUFB;
        #pragma unroll
        for (int i=0;i<4;i++){
            int idx = tid + i*256;
            int row = idx >> 3, seg = idx & 7;
            cp16(base + (uint32_t)(row*HG_STRIDE + seg*8)*2,
                 gB + (size_t)row*EE + seg*8);
        }
    };

    float acc[4][4][4];
    #pragma unroll
    for (int i=0;i<4;i++)
        #pragma unroll
        for (int j=0;j<4;j++)
            #pragma unroll
            for (int p=0;p<4;p++) acc[i][j][p] = 0.f;

    const int lane15 = lane & 15, laneHi = lane >> 4;
    const uint32_t aOff = (uint32_t)((wm*64 + lane15)*HG_STRIDE + laneHi*8)*2;
    const int nr  = (lane & 7) + ((lane >> 4) << 3);
    const int kc8 = ((lane >> 3) & 1) * 8;
    const uint32_t bOff = (uint32_t)((wn*32 + nr)*HG_STRIDE + kc8)*2;

    loadA(0,0); loadB(0,0); cp_commit();
    loadA(1,1); loadB(1,1); cp_commit();

    for (int kc=0; kc<4; kc++){
        int st = kc % 3;
        if (kc < 3) cp_wait<1>(); else cp_wait<0>();
        __syncthreads();
        if (kc + 2 < 4){
            loadA(kc+2, (kc+2)%3);
            loadB(kc+2, (kc+2)%3);
            cp_commit();
        }
        const uint32_t aBase = sb + st*HG_BUFB + aOff;
        const uint32_t bBase = sb + (3+st)*HG_BUFB + bOff;
        #pragma unroll
        for (int k16=0; k16<4; k16++){
            uint32_t af[4][4], bf[2][4];
            #pragma unroll
            for (int mi=0; mi<4; mi++)
                ldsm4(af[mi], aBase + (uint32_t)(mi*16*HG_STRIDE + k16*16)*2);
            #pragma unroll
            for (int ni=0; ni<2; ni++)
                ldsm4(bf[ni], bBase + (uint32_t)(ni*16*HG_STRIDE + k16*16)*2);
            #pragma unroll
            for (int mi=0; mi<4; mi++)
                #pragma unroll
                for (int nt=0; nt<4; nt++)
                    mma16816(acc[mi][nt], af[mi], &bf[nt>>1][(nt&1)*2]);
        }
        if (kc < 3) __syncthreads();
    }

    const int g = lane >> 2, q = lane & 3;
    float2 bias2[4];
    #pragma unroll
    for (int nt=0; nt<4; nt++){
        int col = n0 + wn*32 + nt*8 + q*2;
        bias2[nt] = *(const float2*)(bias0 + col);
    }
    #pragma unroll
    for (int mi=0; mi<4; mi++){
        int r0 = m0 + wm*64 + mi*16 + g;
        int r1 = r0 + 8;
        #pragma unroll
        for (int nt=0; nt<4; nt++){
            int col = n0 + wn*32 + nt*8 + q*2;
            if (r0 < MROWS){
                float2 v = make_float2(acc[mi][nt][0] + bias2[nt].x,
                                       acc[mi][nt][1] + bias2[nt].y);
                *(float2*)(C + (size_t)r0*N3 + col) = v;
            }
            if (r1 < MROWS){
                float2 v = make_float2(acc[mi][nt][2] + bias2[nt].x,
                                       acc[mi][nt][3] + bias2[nt].y);
                *(float2*)(C + (size_t)r1*N3 + col) = v;
            }
        }
    }
}

// ---------------- output GEMM tile (CTA 128x256, warp 64x64) ----------------
__device__ void out_tile(char* sm, uint32_t sb,
                         int tid, int lane, int wid,
                         int m0, int n0,
                         const float* __restrict__ ob,
                         float* __restrict__ C){
    const int wm = wid >> 2, wn = wid & 3;

    auto loadA = [&](int kc, int st){
        const __half* gA = g_Ah + (size_t)m0*UU + kc*64;
        uint32_t base = sb + st*OG_ABUF;
        #pragma unroll
        for (int i=0;i<4;i++){
            int idx = tid + i*256;
            int row = idx >> 3, seg = idx & 7;
            cp16(base + (uint32_t)(row*HG_STRIDE + seg*8)*2,
                 gA + (size_t)row*UU + seg*8);
        }
    };
    auto loadB = [&](int kc, int st){
        const __half* gB = g_Wh + (size_t)n0*UU + kc*64;
        uint32_t base = sb + 3*OG_ABUF + st*OG_BBUF;
        #pragma unroll
        for (int i=0;i<8;i++){
            int idx = tid + i*256;
            int row = idx >> 3, seg = idx & 7;
            cp16(base + (uint32_t)(row*HG_STRIDE + seg*8)*2,
                 gB + (size_t)row*UU + seg*8);
        }
    };

    float acc[4][8][4];
    #pragma unroll
    for (int i=0;i<4;i++)
        #pragma unroll
        for (int j=0;j<8;j++)
            #pragma unroll
            for (int p=0;p<4;p++) acc[i][j][p] = 0.f;

    const int lane15 = lane & 15, laneHi = lane >> 4;
    const uint32_t aOff = (uint32_t)((wm*64 + lane15)*HG_STRIDE + laneHi*8)*2;
    const int nr  = (lane & 7) + ((lane >> 4) << 3);
    const int kc8 = ((lane >> 3) & 1) * 8;
    const uint32_t bOff = (uint32_t)((wn*64 + nr)*HG_STRIDE + kc8)*2;

    loadA(0,0); loadB(0,0); cp_commit();
    loadA(1,1); loadB(1,1); cp_commit();

    for (int kc=0; kc<16; kc++){
        int st = kc % 3;
        if (kc < 15) cp_wait<1>(); else cp_wait<0>();
        __syncthreads();
        if (kc + 2 < 16){
            loadA(kc+2, (kc+2)%3);
            loadB(kc+2, (kc+2)%3);
            cp_commit();
        }

        const uint32_t aBase = sb + st*OG_ABUF + aOff;
        const uint32_t bBase = sb + 3*OG_ABUF + st*OG_BBUF + bOff;
        #pragma unroll
        for (int k16=0; k16<4; k16++){
            uint32_t af[4][4], bf[4][4];
            #pragma unroll
            for (int mi=0; mi<4; mi++)
                ldsm4(af[mi], aBase + (uint32_t)(mi*16*HG_STRIDE + k16*16)*2);
            #pragma unroll
            for (int ni=0; ni<4; ni++)
                ldsm4(bf[ni], bBase + (uint32_t)(ni*16*HG_STRIDE + k16*16)*2);
            #pragma unroll
            for (int mi=0; mi<4; mi++)
                #pragma unroll
                for (int nt=0; nt<8; nt++)
                    mma16816(acc[mi][nt], af[mi], &bf[nt>>1][(nt&1)*2]);
        }
    }

    // epilogue: A-row r = t*16+b -> C-row = b*TT + t, valid iff t < TT
    const int g = lane >> 2, q = lane & 3;
    float2 bias2[8];
    #pragma unroll
    for (int nt=0; nt<8; nt++){
        int col = n0 + wn*64 + nt*8 + q*2;
        bias2[nt] = *(const float2*)(ob + col);
    }
    #pragma unroll
    for (int mi=0; mi<4; mi++){
        int r0 = m0 + wm*64 + mi*16 + g;
        int r1 = r0 + 8;
        int t0 = r0 >> 4, b0 = r0 & 15;
        int t1 = r1 >> 4, b1 = r1 & 15;
        #pragma unroll
        for (int nt=0; nt<8; nt++){
            int col = n0 + wn*64 + nt*8 + q*2;
            if (t0 < TT){
                float2 v = make_float2(acc[mi][nt][0] + bias2[nt].x,
                                       acc[mi][nt][1] + bias2[nt].y);
                *(float2*)(C + (size_t)(b0*TT + t0)*VV + col) = v;
            }
            if (t1 < TT){
                float2 v = make_float2(acc[mi][nt][2] + bias2[nt].x,
                                       acc[mi][nt][3] + bias2[nt].y);
                *(float2*)(C + (size_t)(b1*TT + t1)*VV + col) = v;
            }
        }
    }
}

// ---------------- fused persistent kernel ----------------
// phase 1 (all CTAs): drain xproj tile queue
// then: CTAs 0..63 -> GRU (after xp done) -> join out queue
//       CTAs 64..147 -> convW slice -> out queue
__global__ __launch_bounds__(256,1) void gru_out_fused(
    const float* __restrict__ gbias,
    const int* __restrict__ tok,
    const float* __restrict__ ob,
    const float* __restrict__ oW,
    float* __restrict__ C)
{
    extern __shared__ __align__(128) char smg[];
    __shared__ unsigned s_ti;
    const uint32_t sb0 = smem_to_u32(smg);
    const int tid = threadIdx.x, lane = tid & 31, wrp = tid >> 5, bl = blockIdx.x;

    // ---------------- phase 1: xproj tiles (all CTAs) ----------------
    for(;;){
        if (tid == 0) s_ti = atomicAdd(&g_xtile, 1u);
        __syncthreads();
        unsigned ti = s_ti;
        if (ti >= NXTILES) break;
        int m = (int)(ti & 31), n = (int)(ti >> 5);
        xp_tile(smg, sb0, tid, lane, wrp, m*128, n*128, gbias, g_xproj);
        __syncthreads();
        if (tid == 0) red_rel(&g_xdone);
    }

    if (bl < GRU_BLOCKS){
        // wait for all xproj tiles to be complete + visible
        if (tid == 0){ while (ld_acq(&g_xdone) < NXTILES) {} }
        __syncthreads();

        // ---------------- GRU role ----------------
        __half* Ah = (__half*)smg;                        // [8 warps][16 batches][ASTRIDE]
        float*  sc = (float*)(smg + 8*AWARP*2);           // [8][16][SCSTRIDE]
        const int g = lane >> 2, tig = lane & 3;

        uint32_t bw[8][6][2];
        #pragma unroll
        for (int j=0;j<8;j++)
            #pragma unroll
            for (int nt=0;nt<6;nt++){
                int n_local = nt*8 + g;
                int gate = n_local >> 4, u = n_local & 15;
                const __half* base = g_rkTh + (size_t)(gate*UU + bl*UPC + u)*UU + wrp*128 + j*16 + 2*tig;
                bw[j][nt][0] = *(const uint32_t*)base;
                bw[j][nt][1] = *(const uint32_t*)(base + 8);
            }

        const int eb = tid >> 4, eu = tid & 15;
        const int ecol = bl*UPC + eu;
        const float bz = gbias[N3 + ecol];
        const float br = gbias[N3 + UU + ecol];
        const float bh = gbias[N3 + 2*UU + ecol];
        const uint32_t holdOff = (uint32_t)(((ecol >> 7)*16 + eb)*ASTRIDE + (ecol & 127));

        const uint32_t wbase = sb0 + wrp*AWARP*2;

        for (int t=0; t<TT; t++){
            const int rbuf = t & 1, wbuf = rbuf ^ 1;

            int r = eb*TT + t;
            const float* xp = g_xproj + (size_t)r*N3;
            float xz = xp[ecol], xr = xp[UU+ecol], xh = xp[2*UU+ecol];
            bool msk = (tok[eb*256 + t] != 0);
            bool fl  = (g_flag[r] != 0);

            {
                const char* srcH = (const char*)&g_hfp[rbuf][0] + wrp*256;
                #pragma unroll
                for (int i=0;i<8;i++){
                    int idx = lane + 32*i;
                    int b = idx >> 4, c = idx & 15;
                    cp16(wbase + (uint32_t)(b*ASTRIDE*2 + c*16), srcH + b*2048 + c*16);
                }
                cp_commit(); cp_wait<0>();
                __syncwarp();
            }

            float acc[6][4];
            #pragma unroll
            for (int nt=0;nt<6;nt++)
                #pragma unroll
                for (int p=0;p<4;p++) acc[nt][p] = 0.f;

            const char* Ab = (const char*)smg + wrp*AWARP*2;
            #pragma unroll
            for (int j=0;j<8;j++){
                int koff = j*16 + 2*tig;
                uint32_t a[4];
                a[0] = *(const uint32_t*)(Ab + (size_t)(g*ASTRIDE     + koff    )*2);
                a[1] = *(const uint32_t*)(Ab + (size_t)((g+8)*ASTRIDE + koff    )*2);
                a[2] = *(const uint32_t*)(Ab + (size_t)(g*ASTRIDE     + koff + 8)*2);
                a[3] = *(const uint32_t*)(Ab + (size_t)((g+8)*ASTRIDE + koff + 8)*2);
                #pragma unroll
                for (int nt=0;nt<6;nt++)
                    mma16816(acc[nt], a, bw[j][nt]);
            }

            #pragma unroll
            for (int nt=0;nt<6;nt++){
                int c = nt*8 + 2*tig;
                sc[(wrp*16 + g  )*SCSTRIDE + c    ] = acc[nt][0];
                sc[(wrp*16 + g  )*SCSTRIDE + c + 1] = acc[nt][1];
                sc[(wrp*16 + g+8)*SCSTRIDE + c    ] = acc[nt][2];
                sc[(wrp*16 + g+8)*SCSTRIDE + c + 1] = acc[nt][3];
            }
            __syncthreads();

            {
                float rz = bz, rr = br, rh = bh;
                #pragma unroll
                for (int w=0;w<8;w++){
                    const float* p = &sc[(w*16 + eb)*SCSTRIDE];
                    rz += p[eu]; rr += p[16+eu]; rh += p[32+eu];
                }
                float hold = __half2float(Ah[holdOff]);
                float z  = 1.f/(1.f + __expf(-(xz+rz)));
                float rg = 1.f/(1.f + __expf(-(xr+rr)));
                float e2 = __expf(2.f*(xh + rg*rh));
                float hh = __fdividef(e2 - 1.f, e2 + 1.f);
                float hn = z*hold + (1.f - z)*hh;
                float hnew = msk ? hn : hold;
                __half nh = __float2half(hnew);
                g_hfp[wbuf][eb*UU + ecol] = nh;
                g_Ah[(size_t)(t*16 + eb)*UU + ecol] = fl ? nh : __half(0.f);
            }
            gru_barrier2(bl, t);
        }
        // fall through: join the output tile queue
    } else {
        // ---------------- convW role: transpose out_W [U][V] -> fp16 g_Wh [V][U] ----------------
        float* wt = (float*)smg;   // 32x33 tile
        const int tx = tid & 31, ty = tid >> 5;
        for (int ti = bl - GRU_BLOCKS; ti < 32000; ti += OUT_BLOCKS){
            int n0 = (ti % 1000)*32, k0 = (ti / 1000)*32;
            #pragma unroll
            for (int i=ty; i<32; i+=8)
                wt[i*33+tx] = oW[(size_t)(k0+i)*VV + n0+tx];
            __syncthreads();
            #pragma unroll
            for (int i=ty; i<32; i+=8)
                g_Wh[(size_t)(n0+i)*UU + k0+tx] = __float2half(wt[tx*33+i]);
            __syncthreads();
        }
        if (tid == 0) red_rel(&g_wdone);
    }

    // ---------------- output GEMM role (persistent tile queue) ----------------
    if (tid == 0){ while (ld_acq(&g_wdone) < OUT_BLOCKS) __nanosleep(256); }
    __syncthreads();

    for(;;){
        if (tid == 0) s_ti = atomicAdd(&g_tile, 1u);
        __syncthreads();
        unsigned ti = s_ti;
        if (ti >= NTILES) break;
        int m = (int)(ti / 125), nb = (int)(ti % 125);
        wait_tile_ready(m);
        out_tile(smg, sb0, tid, lane, tid >> 5, m*128, nb*256, ob, C);
        __syncthreads();
    }
}

// ---------------- launch ----------------
extern "C" void kernel_launch(void* const* d_in, const int* in_sizes, int n_in,
                              void* d_out, int out_size)
{
    const float* latent = (const float*)d_in[0];
    const int*   tok    = (const int*)d_in[1];
    const float* emb    = (const float*)d_in[2];
    const float* dW     = (const float*)d_in[3];
    const float* db     = (const float*)d_in[4];
    const float* gk     = (const float*)d_in[5];
    const float* grk    = (const float*)d_in[6];
    const float* gb     = (const float*)d_in[7];
    const float* oW     = (const float*)d_in[8];
    const float* ob     = (const float*)d_in[9];
    float* out = (float*)d_out;

    (void)in_sizes; (void)n_in; (void)out_size;

    cudaFuncSetAttribute(gru_out_fused, cudaFuncAttributeMaxDynamicSharedMemorySize, OG_SMEM);

    // fused prep: tokens/flags, fp16 conversions+transposes, h0, counter resets
    prep_all<<<PB_TOTAL, 256>>>(latent, dW, db, tok, emb, gk, grk);

    // fused persistent xproj + GRU + convW + output GEMM
    gru_out_fused<<<FUSED_BLOCKS, 256, OG_SMEM>>>(gb, tok, ob, oW, out);
}

// round 15
// speedup vs baseline: 1.2023x; 1.2023x over previous
#include <cuda_runtime.h>
#include <cuda_fp16.h>
#include <cstdint>

// Problem constants
#define NB   16          // batch
#define TT   255         // teacher length (T-1)
#define UU   1024        // GRU units
#define VV   32000       // vocab
#define EE   256         // emb dim
#define LATD 512         // latent dim
#define MROWS (NB*TT)    // 4080
#define MPAD 4096
#define N3   (3*UU)      // 3072

#define GRU_BLOCKS 64
#define OUT_BLOCKS 84
#define FUSED_BLOCKS (GRU_BLOCKS+OUT_BLOCKS)
#define NTILES (32*125)                      // 4000 output tiles (m 0..31, nb 0..124)
#define NXTILES (32*24)                      // 768 xproj tiles
#define UPC 16                               // units per CTA
#define SCSTRIDE 52
#define ASTRIDE 136                          // padded halves per (warp,batch) row
#define AWARP   (16*ASTRIDE)                 // halves per warp slice

// ---------------- device scratch (no allocs allowed) ----------------
__device__ __align__(128) __half g_hfp[2][NB*UU];     // fp16 hidden state, ping-pong
__device__ float g_xproj[(size_t)MROWS*N3];           // x @ gru_kernel + b0
__device__ __align__(128) __half g_Ah[(size_t)MPAD*UU];   // fp16 GRU outputs, row = t*16+b
__device__ __align__(128) __half g_Wh[(size_t)VV*UU];     // fp16 out_W^T  [V][U]
__device__ __align__(128) __half g_embh[(size_t)VV*EE];   // fp16 emb
__device__ __align__(128) __half g_gkT[(size_t)N3*EE];    // fp16 gru_kernel^T [3072][256]
__device__ __align__(128) __half g_rkTh[(size_t)N3*UU];   // fp16 gru_rkernel^T [3072][1024]
__device__ int   g_arow[MROWS];
__device__ unsigned char g_flag[MROWS];
__device__ __align__(256) unsigned g_cnt8[8][64];     // two-level barrier counters (256B apart)
__device__ unsigned g_tile;                           // output tile work queue
__device__ unsigned g_xtile;                          // xproj tile work queue
__device__ unsigned g_xdone;                          // xproj tiles completed

// ---------------- PTX helpers ----------------
__device__ __forceinline__ uint32_t smem_to_u32(const void* p){
    uint32_t a;
    asm("{ .reg .u64 t; cvta.to.shared.u64 t, %1; cvt.u32.u64 %0, t; }" : "=r"(a) : "l"(p));
    return a;
}
__device__ __forceinline__ void cp16(uint32_t s, const void* g){
    asm volatile("cp.async.cg.shared.global [%0], [%1], 16;" :: "r"(s), "l"(g));
}
__device__ __forceinline__ void cp_commit(){ asm volatile("cp.async.commit_group;" ::: "memory"); }
template<int N> __device__ __forceinline__ void cp_wait(){
    asm volatile("cp.async.wait_group %0;" :: "n"(N) : "memory");
}
__device__ __forceinline__ void ldsm4(uint32_t* r, uint32_t addr){
    asm volatile("ldmatrix.sync.aligned.m8n8.x4.shared.b16 {%0,%1,%2,%3}, [%4];"
        : "=r"(r[0]),"=r"(r[1]),"=r"(r[2]),"=r"(r[3]) : "r"(addr));
}
__device__ __forceinline__ void mma16816(float* c, const uint32_t* a, const uint32_t* b){
    asm volatile("mma.sync.aligned.m16n8k16.row.col.f32.f16.f16.f32 "
        "{%0,%1,%2,%3}, {%4,%5,%6,%7}, {%8,%9}, {%0,%1,%2,%3};"
        : "+f"(c[0]), "+f"(c[1]), "+f"(c[2]), "+f"(c[3])
        : "r"(a[0]), "r"(a[1]), "r"(a[2]), "r"(a[3]), "r"(b[0]), "r"(b[1]));
}
__device__ __forceinline__ void red_rel(unsigned* p){
    asm volatile("red.release.gpu.add.u32 [%0], 1;" :: "l"(p) : "memory");
}
__device__ __forceinline__ unsigned ld_acq(const unsigned* p){
    unsigned v;
    asm volatile("ld.acquire.gpu.u32 %0, [%1];" : "=r"(v) : "l"(p) : "memory");
    return v;
}

// two-level grid barrier: 8 counters (8 CTAs each), threads 0-7 spin one counter each.
__device__ __forceinline__ void gru_barrier2(int bl, int t){
    __syncthreads();
    if (threadIdx.x == 0) red_rel(&g_cnt8[bl & 7][0]);
    if (threadIdx.x < 8){
        unsigned target = (unsigned)(GRU_BLOCKS/8)*(unsigned)(t+1);
        const unsigned* p = &g_cnt8[threadIdx.x][0];
        while (ld_acq(p) < target) {}
    }
    __syncthreads();
}

// out-role readiness: all 8 counters >= min(64*(m+1), 8*TT)
__device__ __forceinline__ void wait_tile_ready(int m){
    if (threadIdx.x < 8){
        unsigned target = 64u*(unsigned)(m+1);
        unsigned maxt = 8u*(unsigned)TT;
        if (target > maxt) target = maxt;
        const unsigned* p = &g_cnt8[threadIdx.x][0];
        while (ld_acq(p) < target) __nanosleep(256);
    }
    __syncthreads();
}

// ---------------- fused prep kernel (convW restored here: 32000 parallel blocks) ----------------
#define PB_PREP 1
#define PB_EMB  8000
#define PB_GKT  768
#define PB_H0   64
#define PB_RKT  3072
#define PB_W    32000
#define PB_TOTAL (PB_PREP+PB_EMB+PB_GKT+PB_H0+PB_RKT+PB_W)

__global__ void prep_all(const float* __restrict__ lat, const float* __restrict__ dW,
                         const float* __restrict__ db,  const int* __restrict__ tok,
                         const float* __restrict__ emb, const float* __restrict__ gk,
                         const float* __restrict__ grk, const float* __restrict__ oW){
    __shared__ float tile[32][33];
    int bid = blockIdx.x;
    const int tid = threadIdx.x;
    const int tx = tid & 31, ty = tid >> 5;

    if (bid < PB_PREP){
        if (tid < 8) g_cnt8[tid][0] = 0;
        if (tid == 8){ g_tile = 0; g_xtile = 0; g_xdone = 0; }
        if (tid >= 32 && tid < 32+NB){
            int b = tid - 32;
            unsigned char f = 0;
            for (int t=0;t<TT;t++){
                f |= (tok[b*256 + t] != 0) ? 1 : 0;
                g_flag[b*TT + t] = f;
            }
        }
        for (int m=tid; m<MROWS; m+=256){
            int v = tok[(m/TT)*256 + (m%TT)];
            if (v < 0) v = 0;
            if (v >= VV) v = VV-1;
            g_arow[m] = v;
        }
        return;
    }
    bid -= PB_PREP;

    if (bid < PB_EMB){
        int i = bid*256 + tid;
        float4 v = ((const float4*)emb)[i];
        __half2* dst = (__half2*)g_embh;
        dst[i*2+0] = __floats2half2_rn(v.x, v.y);
        dst[i*2+1] = __floats2half2_rn(v.z, v.w);
        return;
    }
    bid -= PB_EMB;

    if (bid < PB_GKT){
        int n0 = (bid % 96)*32, k0 = (bid / 96)*32;
        #pragma unroll
        for (int i=ty; i<32; i+=8)
            tile[i][tx] = gk[(size_t)(k0+i)*N3 + n0+tx];
        __syncthreads();
        #pragma unroll
        for (int i=ty; i<32; i+=8)
            g_gkT[(size_t)(n0+i)*EE + k0+tx] = __float2half(tile[tx][i]);
        return;
    }
    bid -= PB_GKT;

    if (bid < PB_H0){
        int o = bid*256 + tid;
        int b = o >> 10, u = o & (UU-1);
        float acc = db[u];
        const float* lrow = lat + b*LATD;
        #pragma unroll 8
        for (int k=0;k<LATD;k++) acc = fmaf(lrow[k], dW[(size_t)k*UU + u], acc);
        g_hfp[0][b*UU + u] = __float2half(acc);
        return;
    }
    bid -= PB_H0;

    if (bid < PB_RKT){
        int n0 = (bid % 96)*32, k0 = (bid / 96)*32;
        #pragma unroll
        for (int i=ty; i<32; i+=8)
            tile[i][tx] = grk[(size_t)(k0+i)*N3 + n0+tx];
        __syncthreads();
        #pragma unroll
        for (int i=ty; i<32; i+=8)
            g_rkTh[(size_t)(n0+i)*UU + k0+tx] = __float2half(tile[tx][i]);
        return;
    }
    bid -= PB_RKT;

    {   // convW: transpose out_W [U][V] -> fp16 g_Wh [V][U]
        int n0 = (bid % 1000)*32, k0 = (bid / 1000)*32;
        #pragma unroll
        for (int i=ty; i<32; i+=8)
            tile[i][tx] = oW[(size_t)(k0+i)*VV + n0+tx];
        __syncthreads();
        #pragma unroll
        for (int i=ty; i<32; i+=8)
            g_Wh[(size_t)(n0+i)*UU + k0+tx] = __float2half(tile[tx][i]);
        return;
    }
}

// ---------------- HMMA tile constants ----------------
#define HG_STRIDE 72
#define HG_BUFB   (128*HG_STRIDE*2)       // 18432
#define OG_ABUF   HG_BUFB
#define OG_BBUF   (256*HG_STRIDE*2)       // 36864
#define OG_SMEM   (3*OG_ABUF + 3*OG_BBUF) // 165888

// ---------------- xproj tile (128x128, K=256, gathered A) ----------------
__device__ void xp_tile(char* sm, uint32_t sb, int tid, int lane, int wid,
                        int m0, int n0, const float* __restrict__ bias0,
                        float* __restrict__ C){
    const int wm = wid >> 2, wn = wid & 3;

    const __half* aptr[4];
    int asegs[4];
    #pragma unroll
    for (int i=0;i<4;i++){
        int idx = tid + i*256;
        int row = idx >> 3; asegs[i] = idx & 7;
        int grow = m0 + row;
        int tokv = (grow < MROWS) ? g_arow[grow] : 0;
        aptr[i] = g_embh + (size_t)tokv*EE;
    }
    auto loadA = [&](int kc, int st){
        uint32_t base = sb + st*HG_BUFB;
        #pragma unroll
        for (int i=0;i<4;i++){
            int idx = tid + i*256;
            int row = idx >> 3;
            cp16(base + (uint32_t)(row*HG_STRIDE + asegs[i]*8)*2,
                 aptr[i] + kc*64 + asegs[i]*8);
        }
    };
    auto loadB = [&](int kc, int st){
        const __half* gB = g_gkT + (size_t)n0*EE + kc*64;
        uint32_t base = sb + (3+st)*HG_BUFB;
        #pragma unroll
        for (int i=0;i<4;i++){
            int idx = tid + i*256;
            int row = idx >> 3, seg = idx & 7;
            cp16(base + (uint32_t)(row*HG_STRIDE + seg*8)*2,
                 gB + (size_t)row*EE + seg*8);
        }
    };

    float acc[4][4][4];
    #pragma unroll
    for (int i=0;i<4;i++)
        #pragma unroll
        for (int j=0;j<4;j++)
            #pragma unroll
            for (int p=0;p<4;p++) acc[i][j][p] = 0.f;

    const int lane15 = lane & 15, laneHi = lane >> 4;
    const uint32_t aOff = (uint32_t)((wm*64 + lane15)*HG_STRIDE + laneHi*8)*2;
    const int nr  = (lane & 7) + ((lane >> 4) << 3);
    const int kc8 = ((lane >> 3) & 1) * 8;
    const uint32_t bOff = (uint32_t)((wn*32 + nr)*HG_STRIDE + kc8)*2;

    loadA(0,0); loadB(0,0); cp_commit();
    loadA(1,1); loadB(1,1); cp_commit();

    for (int kc=0; kc<4; kc++){
        int st = kc % 3;
        if (kc < 3) cp_wait<1>(); else cp_wait<0>();
        __syncthreads();
        if (kc + 2 < 4){
            loadA(kc+2, (kc+2)%3);
            loadB(kc+2, (kc+2)%3);
            cp_commit();
        }
        const uint32_t aBase = sb + st*HG_BUFB + aOff;
        const uint32_t bBase = sb + (3+st)*HG_BUFB + bOff;
        #pragma unroll
        for (int k16=0; k16<4; k16++){
            uint32_t af[4][4], bf[2][4];
            #pragma unroll
            for (int mi=0; mi<4; mi++)
                ldsm4(af[mi], aBase + (uint32_t)(mi*16*HG_STRIDE + k16*16)*2);
            #pragma unroll
            for (int ni=0; ni<2; ni++)
                ldsm4(bf[ni], bBase + (uint32_t)(ni*16*HG_STRIDE + k16*16)*2);
            #pragma unroll
            for (int mi=0; mi<4; mi++)
                #pragma unroll
                for (int nt=0; nt<4; nt++)
                    mma16816(acc[mi][nt], af[mi], &bf[nt>>1][(nt&1)*2]);
        }
        if (kc < 3) __syncthreads();
    }

    const int g = lane >> 2, q = lane & 3;
    float2 bias2[4];
    #pragma unroll
    for (int nt=0; nt<4; nt++){
        int col = n0 + wn*32 + nt*8 + q*2;
        bias2[nt] = *(const float2*)(bias0 + col);
    }
    #pragma unroll
    for (int mi=0; mi<4; mi++){
        int r0 = m0 + wm*64 + mi*16 + g;
        int r1 = r0 + 8;
        #pragma unroll
        for (int nt=0; nt<4; nt++){
            int col = n0 + wn*32 + nt*8 + q*2;
            if (r0 < MROWS){
                float2 v = make_float2(acc[mi][nt][0] + bias2[nt].x,
                                       acc[mi][nt][1] + bias2[nt].y);
                *(float2*)(C + (size_t)r0*N3 + col) = v;
            }
            if (r1 < MROWS){
                float2 v = make_float2(acc[mi][nt][2] + bias2[nt].x,
                                       acc[mi][nt][3] + bias2[nt].y);
                *(float2*)(C + (size_t)r1*N3 + col) = v;
            }
        }
    }
}

// ---------------- output GEMM tile (CTA 128x256, warp 64x64) ----------------
__device__ void out_tile(char* sm, uint32_t sb,
                         int tid, int lane, int wid,
                         int m0, int n0,
                         const float* __restrict__ ob,
                         float* __restrict__ C){
    const int wm = wid >> 2, wn = wid & 3;

    auto loadA = [&](int kc, int st){
        const __half* gA = g_Ah + (size_t)m0*UU + kc*64;
        uint32_t base = sb + st*OG_ABUF;
        #pragma unroll
        for (int i=0;i<4;i++){
            int idx = tid + i*256;
            int row = idx >> 3, seg = idx & 7;
            cp16(base + (uint32_t)(row*HG_STRIDE + seg*8)*2,
                 gA + (size_t)row*UU + seg*8);
        }
    };
    auto loadB = [&](int kc, int st){
        const __half* gB = g_Wh + (size_t)n0*UU + kc*64;
        uint32_t base = sb + 3*OG_ABUF + st*OG_BBUF;
        #pragma unroll
        for (int i=0;i<8;i++){
            int idx = tid + i*256;
            int row = idx >> 3, seg = idx & 7;
            cp16(base + (uint32_t)(row*HG_STRIDE + seg*8)*2,
                 gB + (size_t)row*UU + seg*8);
        }
    };

    float acc[4][8][4];
    #pragma unroll
    for (int i=0;i<4;i++)
        #pragma unroll
        for (int j=0;j<8;j++)
            #pragma unroll
            for (int p=0;p<4;p++) acc[i][j][p] = 0.f;

    const int lane15 = lane & 15, laneHi = lane >> 4;
    const uint32_t aOff = (uint32_t)((wm*64 + lane15)*HG_STRIDE + laneHi*8)*2;
    const int nr  = (lane & 7) + ((lane >> 4) << 3);
    const int kc8 = ((lane >> 3) & 1) * 8;
    const uint32_t bOff = (uint32_t)((wn*64 + nr)*HG_STRIDE + kc8)*2;

    loadA(0,0); loadB(0,0); cp_commit();
    loadA(1,1); loadB(1,1); cp_commit();

    for (int kc=0; kc<16; kc++){
        int st = kc % 3;
        if (kc < 15) cp_wait<1>(); else cp_wait<0>();
        __syncthreads();
        if (kc + 2 < 16){
            loadA(kc+2, (kc+2)%3);
            loadB(kc+2, (kc+2)%3);
            cp_commit();
        }

        const uint32_t aBase = sb + st*OG_ABUF + aOff;
        const uint32_t bBase = sb + 3*OG_ABUF + st*OG_BBUF + bOff;
        #pragma unroll
        for (int k16=0; k16<4; k16++){
            uint32_t af[4][4], bf[4][4];
            #pragma unroll
            for (int mi=0; mi<4; mi++)
                ldsm4(af[mi], aBase + (uint32_t)(mi*16*HG_STRIDE + k16*16)*2);
            #pragma unroll
            for (int ni=0; ni<4; ni++)
                ldsm4(bf[ni], bBase + (uint32_t)(ni*16*HG_STRIDE + k16*16)*2);
            #pragma unroll
            for (int mi=0; mi<4; mi++)
                #pragma unroll
                for (int nt=0; nt<8; nt++)
                    mma16816(acc[mi][nt], af[mi], &bf[nt>>1][(nt&1)*2]);
        }
    }

    // epilogue: A-row r = t*16+b -> C-row = b*TT + t, valid iff t < TT
    const int g = lane >> 2, q = lane & 3;
    float2 bias2[8];
    #pragma unroll
    for (int nt=0; nt<8; nt++){
        int col = n0 + wn*64 + nt*8 + q*2;
        bias2[nt] = *(const float2*)(ob + col);
    }
    #pragma unroll
    for (int mi=0; mi<4; mi++){
        int r0 = m0 + wm*64 + mi*16 + g;
        int r1 = r0 + 8;
        int t0 = r0 >> 4, b0 = r0 & 15;
        int t1 = r1 >> 4, b1 = r1 & 15;
        #pragma unroll
        for (int nt=0; nt<8; nt++){
            int col = n0 + wn*64 + nt*8 + q*2;
            if (t0 < TT){
                float2 v = make_float2(acc[mi][nt][0] + bias2[nt].x,
                                       acc[mi][nt][1] + bias2[nt].y);
                *(float2*)(C + (size_t)(b0*TT + t0)*VV + col) = v;
            }
            if (t1 < TT){
                float2 v = make_float2(acc[mi][nt][2] + bias2[nt].x,
                                       acc[mi][nt][3] + bias2[nt].y);
                *(float2*)(C + (size_t)(b1*TT + t1)*VV + col) = v;
            }
        }
    }
}

// ---------------- fused persistent kernel ----------------
// phase 1 (all CTAs): drain xproj tile queue
// then: CTAs 0..63 -> GRU (after xp done) -> join out queue
//       CTAs 64..147 -> out queue immediately
__global__ __launch_bounds__(256,1) void gru_out_fused(
    const float* __restrict__ gbias,
    const int* __restrict__ tok,
    const float* __restrict__ ob,
    float* __restrict__ C)
{
    extern __shared__ __align__(128) char smg[];
    __shared__ unsigned s_ti;
    const uint32_t sb0 = smem_to_u32(smg);
    const int tid = threadIdx.x, lane = tid & 31, wrp = tid >> 5, bl = blockIdx.x;

    // ---------------- phase 1: xproj tiles (all CTAs) ----------------
    for(;;){
        if (tid == 0) s_ti = atomicAdd(&g_xtile, 1u);
        __syncthreads();
        unsigned ti = s_ti;
        if (ti >= NXTILES) break;
        int m = (int)(ti & 31), n = (int)(ti >> 5);
        xp_tile(smg, sb0, tid, lane, wrp, m*128, n*128, gbias, g_xproj);
        __syncthreads();
        if (tid == 0) red_rel(&g_xdone);
    }

    if (bl < GRU_BLOCKS){
        // wait for all xproj tiles to be complete + visible
        if (tid == 0){ while (ld_acq(&g_xdone) < NXTILES) {} }
        __syncthreads();

        // ---------------- GRU role ----------------
        __half* Ah = (__half*)smg;                        // [8 warps][16 batches][ASTRIDE]
        float*  sc = (float*)(smg + 8*AWARP*2);           // [8][16][SCSTRIDE]
        const int g = lane >> 2, tig = lane & 3;

        uint32_t bw[8][6][2];
        #pragma unroll
        for (int j=0;j<8;j++)
            #pragma unroll
            for (int nt=0;nt<6;nt++){
                int n_local = nt*8 + g;
                int gate = n_local >> 4, u = n_local & 15;
                const __half* base = g_rkTh + (size_t)(gate*UU + bl*UPC + u)*UU + wrp*128 + j*16 + 2*tig;
                bw[j][nt][0] = *(const uint32_t*)base;
                bw[j][nt][1] = *(const uint32_t*)(base + 8);
            }

        const int eb = tid >> 4, eu = tid & 15;
        const int ecol = bl*UPC + eu;
        const float bz = gbias[N3 + ecol];
        const float br = gbias[N3 + UU + ecol];
        const float bh = gbias[N3 + 2*UU + ecol];
        const uint32_t holdOff = (uint32_t)(((ecol >> 7)*16 + eb)*ASTRIDE + (ecol & 127));

        const uint32_t wbase = sb0 + wrp*AWARP*2;

        for (int t=0; t<TT; t++){
            const int rbuf = t & 1, wbuf = rbuf ^ 1;

            int r = eb*TT + t;
            const float* xp = g_xproj + (size_t)r*N3;
            float xz = xp[ecol], xr = xp[UU+ecol], xh = xp[2*UU+ecol];
            bool msk = (tok[eb*256 + t] != 0);
            bool fl  = (g_flag[r] != 0);

            {
                const char* srcH = (const char*)&g_hfp[rbuf][0] + wrp*256;
                #pragma unroll
                for (int i=0;i<8;i++){
                    int idx = lane + 32*i;
                    int b = idx >> 4, c = idx & 15;
                    cp16(wbase + (uint32_t)(b*ASTRIDE*2 + c*16), srcH + b*2048 + c*16);
                }
                cp_commit(); cp_wait<0>();
                __syncwarp();
            }

            float acc[6][4];
            #pragma unroll
            for (int nt=0;nt<6;nt++)
                #pragma unroll
                for (int p=0;p<4;p++) acc[nt][p] = 0.f;

            const char* Ab = (const char*)smg + wrp*AWARP*2;
            #pragma unroll
            for (int j=0;j<8;j++){
                int koff = j*16 + 2*tig;
                uint32_t a[4];
                a[0] = *(const uint32_t*)(Ab + (size_t)(g*ASTRIDE     + koff    )*2);
                a[1] = *(const uint32_t*)(Ab + (size_t)((g+8)*ASTRIDE + koff    )*2);
                a[2] = *(const uint32_t*)(Ab + (size_t)(g*ASTRIDE     + koff + 8)*2);
                a[3] = *(const uint32_t*)(Ab + (size_t)((g+8)*ASTRIDE + koff + 8)*2);
                #pragma unroll
                for (int nt=0;nt<6;nt++)
                    mma16816(acc[nt], a, bw[j][nt]);
            }

            #pragma unroll
            for (int nt=0;nt<6;nt++){
                int c = nt*8 + 2*tig;
                sc[(wrp*16 + g  )*SCSTRIDE + c    ] = acc[nt][0];
                sc[(wrp*16 + g  )*SCSTRIDE + c + 1] = acc[nt][1];
                sc[(wrp*16 + g+8)*SCSTRIDE + c    ] = acc[nt][2];
                sc[(wrp*16 + g+8)*SCSTRIDE + c + 1] = acc[nt][3];
            }
            __syncthreads();

            {
                float rz = bz, rr = br, rh = bh;
                #pragma unroll
                for (int w=0;w<8;w++){
                    const float* p = &sc[(w*16 + eb)*SCSTRIDE];
                    rz += p[eu]; rr += p[16+eu]; rh += p[32+eu];
                }
                float hold = __half2float(Ah[holdOff]);
                float z  = 1.f/(1.f + __expf(-(xz+rz)));
                float rg = 1.f/(1.f + __expf(-(xr+rr)));
                float e2 = __expf(2.f*(xh + rg*rh));
                float hh = __fdividef(e2 - 1.f, e2 + 1.f);
                float hn = z*hold + (1.f - z)*hh;
                float hnew = msk ? hn : hold;
                __half nh = __float2half(hnew);
                g_hfp[wbuf][eb*UU + ecol] = nh;
                g_Ah[(size_t)(t*16 + eb)*UU + ecol] = fl ? nh : __half(0.f);
            }
            gru_barrier2(bl, t);
        }
        // fall through: join the output tile queue
    }

    // ---------------- output GEMM role (persistent tile queue) ----------------
    for(;;){
        if (tid == 0) s_ti = atomicAdd(&g_tile, 1u);
        __syncthreads();
        unsigned ti = s_ti;
        if (ti >= NTILES) break;
        int m = (int)(ti / 125), nb = (int)(ti % 125);
        wait_tile_ready(m);
        out_tile(smg, sb0, tid, lane, tid >> 5, m*128, nb*256, ob, C);
        __syncthreads();
    }
}

// ---------------- launch ----------------
extern "C" void kernel_launch(void* const* d_in, const int* in_sizes, int n_in,
                              void* d_out, int out_size)
{
    const float* latent = (const float*)d_in[0];
    const int*   tok    = (const int*)d_in[1];
    const float* emb    = (const float*)d_in[2];
    const float* dW     = (const float*)d_in[3];
    const float* db     = (const float*)d_in[4];
    const float* gk     = (const float*)d_in[5];
    const float* grk    = (const float*)d_in[6];
    const float* gb     = (const float*)d_in[7];
    const float* oW     = (const float*)d_in[8];
    const float* ob     = (const float*)d_in[9];
    float* out = (float*)d_out;

    (void)in_sizes; (void)n_in; (void)out_size;

    cudaFuncSetAttribute(gru_out_fused, cudaFuncAttributeMaxDynamicSharedMemorySize, OG_SMEM);

    // fused prep: tokens/flags, fp16 conversions+transposes, h0, convW, counter resets
    prep_all<<<PB_TOTAL, 256>>>(latent, dW, db, tok, emb, gk, grk, oW);

    // fused persistent xproj + GRU + output GEMM
    gru_out_fused<<<FUSED_BLOCKS, 256, OG_SMEM>>>(gb, tok, ob, out);
}